// round 11
// baseline (speedup 1.0000x reference)
#include <cuda_runtime.h>
#include <cuda_fp16.h>
#include <cstdint>

typedef unsigned long long ull;

// Problem shape (fixed by the dataset)
#define NN 50000     // nodes
#define KK 256       // in feats
#define MM 128       // out feats
#define EE 800000    // edges

// Static scratch (no allocs allowed). Zero-initialized at load; reduce_kernel
// restores g_cnt to zero each launch, so the hist invariant holds every call.
__device__ __half g_hw[(size_t)NN * MM];  // h @ W in fp16 (12.8 MB, L2-resident)
__device__ int   g_cnt[NN];               // degree histogram (zero at entry)
__device__ int   g_off[NN];               // CSR exclusive offsets
__device__ int   g_pos[NN];               // fill cursors
__device__ int   g_srcs[EE];              // src ids grouped by dst
// Lane-ordered tf32 B-fragment table (built by prep_kernel blocks 0..63)
__device__ float4 g_wfrag4[32 * 512 / 2];        // 128 KB

__device__ __forceinline__ unsigned f2tf32(float x) {
    unsigned r;
    asm("cvt.rna.tf32.f32 %0, %1;" : "=r"(r) : "f"(x));
    return r;
}

// ---------------------------------------------------------------------------
// K0: prep — blocks 0..63 build W-fragment table; blocks 64.. histogram dst.
// ---------------------------------------------------------------------------
#define WFRAG_BLOCKS 64
__global__ __launch_bounds__(256)
void prep_kernel(const float* __restrict__ W, const int* __restrict__ dst, int E) {
    if (blockIdx.x < WFRAG_BLOCKS) {
        const int idx = blockIdx.x * 256 + threadIdx.x;   // 0 .. 16383
        const int kg = idx >> 9;          // k-step group 0..31
        const int r  = idx & 511;
        const int nt = r >> 5;            // 0..15
        const int le = r & 31;
        const int lq  = le & 3;
        const int ll4 = le >> 2;
        const int col = nt * 8 + ll4;
        const int k0  = kg * 8 + lq;
        float2* out = (float2*)g_wfrag4;
        out[idx] = make_float2(
            __uint_as_float(f2tf32(W[k0 * MM + col])),
            __uint_as_float(f2tf32(W[(k0 + 4) * MM + col])));
    } else {
        const int e = (blockIdx.x - WFRAG_BLOCKS) * 256 + threadIdx.x;
        if (e < E) atomicAdd(&g_cnt[dst[e]], 1);
    }
}

// ---------------------------------------------------------------------------
// K1: block 0 = full exclusive scan of g_cnt -> g_off,g_pos (prefetch-pipelined,
//     hidden under GEMM); blocks 1..782 = hw = h @ W via mma.sync m16n8k8 tf32.
// ---------------------------------------------------------------------------
#define HS_PAD 68
#define HS_FLOATS (64 * HS_PAD)                     // 4352 floats = 17408 B
#define GEMM_SMEM (HS_FLOATS * 4 + 8 * 512 * 8)     // 17408 + 32768 = 50176 B
#define SCAN_TILES ((NN + 511) / 512)               // 98
#define SCAN_PF 8

__device__ __forceinline__ int4 scan_load_tile(int t, int tid) {
    const int base = t * 512 + tid * 4;
    if (base + 3 < NN) return *(const int4*)&g_cnt[base];
    int4 v;
    v.x = (base     < NN) ? g_cnt[base]     : 0;
    v.y = (base + 1 < NN) ? g_cnt[base + 1] : 0;
    v.z = (base + 2 < NN) ? g_cnt[base + 2] : 0;
    v.w = (base + 3 < NN) ? g_cnt[base + 3] : 0;
    return v;
}

__device__ void scan_block_50k() {
    __shared__ int warp_tot[4];
    const int tid  = threadIdx.x;
    const int lane = tid & 31;
    const int warp = tid >> 5;
    int running = 0;

    int4 buf[SCAN_PF];
    #pragma unroll
    for (int t = 0; t < SCAN_PF; t++) buf[t] = scan_load_tile(t, tid);

    for (int tb = 0; tb < SCAN_TILES; tb += SCAN_PF) {
        #pragma unroll
        for (int j = 0; j < SCAN_PF; j++) {
            const int tile = tb + j;
            if (tile >= SCAN_TILES) break;
            const int4 v = buf[j];
            if (tile + SCAN_PF < SCAN_TILES)
                buf[j] = scan_load_tile(tile + SCAN_PF, tid);

            const int s0 = v.x, s1 = s0 + v.y, s2 = s1 + v.z, s3 = s2 + v.w;
            int x = s3;
            #pragma unroll
            for (int off = 1; off < 32; off <<= 1) {
                int y = __shfl_up_sync(0xffffffffu, x, off);
                if (lane >= off) x += y;
            }
            if (lane == 31) warp_tot[warp] = x;
            __syncthreads();
            int wb = 0;
            #pragma unroll
            for (int w = 0; w < 4; w++) if (w < warp) wb += warp_tot[w];
            const int tile_total = warp_tot[0] + warp_tot[1] + warp_tot[2] + warp_tot[3];
            const int bx = running + wb + (x - s3);

            const int base = tile * 512 + tid * 4;
            if (base     < NN) { g_off[base]     = bx;      g_pos[base]     = bx;      }
            if (base + 1 < NN) { g_off[base + 1] = bx + s0; g_pos[base + 1] = bx + s0; }
            if (base + 2 < NN) { g_off[base + 2] = bx + s1; g_pos[base + 2] = bx + s1; }
            if (base + 3 < NN) { g_off[base + 3] = bx + s2; g_pos[base + 3] = bx + s2; }

            running += tile_total;
            __syncthreads();
        }
    }
}

__global__ __launch_bounds__(128, 4)
void gemm_scan_kernel(const float* __restrict__ h) {
    if (blockIdx.x == 0) { scan_block_50k(); return; }

    extern __shared__ float smem[];
    float*  hs  = smem;                          // [64][HS_PAD]
    float2* Wk  = (float2*)(smem + HS_FLOATS);   // [8][512]
    float4* Wk4 = (float4*)Wk;

    const int tid  = threadIdx.x;
    const int warp = tid >> 5;
    const int lane = tid & 31;
    const int q    = lane & 3;    // k-offset within frag
    const int l4   = lane >> 2;   // row/col group

    const int blk_row0 = (blockIdx.x - 1) * 64;

    float d[16][4];
    #pragma unroll
    for (int nt = 0; nt < 16; nt++)
        #pragma unroll
        for (int j = 0; j < 4; j++) d[nt][j] = 0.f;

    for (int kc = 0; kc < 4; kc++) {            // 4 chunks of K=64
        if (kc) __syncthreads();                // drain readers before restage

        // stage B fragments: coalesced float4 copy (2048 float4, 16/thread)
        {
            const float4* src = g_wfrag4 + kc * (8 * 512 / 2);
            #pragma unroll
            for (int i = 0; i < 16; i++)
                Wk4[tid + i * 128] = __ldg(src + tid + i * 128);
        }
        // stage h chunk: 64 rows x 64 cols, tf32-converted (1024 float4, 8/thread)
        #pragma unroll
        for (int i = 0; i < 8; i++) {
            const int e   = tid + i * 128;      // 0..1023
            const int row = e >> 4;
            const int f4  = e & 15;
            int rg = blk_row0 + row;
            if (rg >= NN) rg = NN - 1;
            float4 v = __ldg((const float4*)(h + (size_t)rg * KK + kc * 64) + f4);
            v.x = __uint_as_float(f2tf32(v.x));
            v.y = __uint_as_float(f2tf32(v.y));
            v.z = __uint_as_float(f2tf32(v.z));
            v.w = __uint_as_float(f2tf32(v.w));
            ((float4*)(hs + row * HS_PAD))[f4] = v;
        }
        __syncthreads();

        #pragma unroll
        for (int ks = 0; ks < 8; ks++) {        // 8 k-steps of 8
            const int k8 = ks * 8;
            const int ar = warp * 16 + l4;
            const unsigned a0 = __float_as_uint(hs[(ar    ) * HS_PAD + k8 + q    ]);
            const unsigned a1 = __float_as_uint(hs[(ar + 8) * HS_PAD + k8 + q    ]);
            const unsigned a2 = __float_as_uint(hs[(ar    ) * HS_PAD + k8 + q + 4]);
            const unsigned a3 = __float_as_uint(hs[(ar + 8) * HS_PAD + k8 + q + 4]);
            const float2* wrow = Wk + ks * 512;

            #pragma unroll
            for (int nt = 0; nt < 16; nt++) {
                const float2 bb = wrow[nt * 32 + lane];   // coalesced LDS.64
                asm("mma.sync.aligned.m16n8k8.row.col.f32.tf32.tf32.f32 "
                    "{%0,%1,%2,%3}, {%4,%5,%6,%7}, {%8,%9}, {%0,%1,%2,%3};"
                    : "+f"(d[nt][0]), "+f"(d[nt][1]),
                      "+f"(d[nt][2]), "+f"(d[nt][3])
                    : "r"(a0), "r"(a1), "r"(a2), "r"(a3),
                      "r"(__float_as_uint(bb.x)), "r"(__float_as_uint(bb.y)));
            }
        }
    }

    // epilogue: fp16 store. d0,d1 at (l4, 2q..2q+1), d2,d3 at (l4+8, ..)
    const int r0 = blk_row0 + warp * 16 + l4;
    #pragma unroll
    for (int nt = 0; nt < 16; nt++) {
        const int col = nt * 8 + q * 2;
        if (r0 < NN)
            *(__half2*)(g_hw + (size_t)r0 * MM + col) =
                __floats2half2_rn(d[nt][0], d[nt][1]);
        if (r0 + 8 < NN)
            *(__half2*)(g_hw + (size_t)(r0 + 8) * MM + col) =
                __floats2half2_rn(d[nt][2], d[nt][3]);
    }
}

// ---------------------------------------------------------------------------
// K2: fill — bucket src ids into CSR order
// ---------------------------------------------------------------------------
__global__ void fill_kernel(const int* __restrict__ src, const int* __restrict__ dst, int E) {
    int e = blockIdx.x * blockDim.x + threadIdx.x;
    if (e < E) {
        int p = atomicAdd(&g_pos[dst[e]], 1);
        g_srcs[p] = src[e];
    }
}

// ---------------------------------------------------------------------------
// K3: segmented reduce v3 — one warp per node, 16 gathers genuinely in flight.
//   __launch_bounds__(128, 6) -> ~85-reg budget so ptxas keeps the whole
//   uint2 v[16] burst + addresses live (R10's 40-reg budget serialized it).
//   Ids: one coalesced lane-load + shfl. Remainder: warp-uniform predicated
//   loads (@P LDG issues nothing when off) — no wasted traffic, no divergence.
// ---------------------------------------------------------------------------
__global__ __launch_bounds__(128, 6)
void reduce_kernel(const float* __restrict__ b, float* __restrict__ out) {
    const int n = (int)((blockIdx.x * 128u + threadIdx.x) >> 5);
    if (n >= NN) return;
    const int lane = threadIdx.x & 31;

    const int beg = g_off[n];
    const int deg = g_cnt[n];
    if (lane == 0) g_cnt[n] = 0;   // restore invariant for next launch

    float4 acc = make_float4(0.f, 0.f, 0.f, 0.f);
    const uint2* __restrict__ hwp = (const uint2*)g_hw;   // 32 uint2 per row

    for (int base = 0; base < deg; base += 16) {
        const int m = min(deg - base, 16);   // warp-uniform
        int myid = 0;
        if (lane < m) myid = __ldg(&g_srcs[beg + base + lane]);

        uint2 v[16];
        #pragma unroll
        for (int j = 0; j < 16; j++) {
            v[j] = make_uint2(0u, 0u);
            if (j < m) {                      // uniform predicate -> @P LDG
                const int s = __shfl_sync(0xffffffffu, myid, j);
                v[j] = __ldg(hwp + (size_t)s * 32 + lane);
            }
        }
        #pragma unroll
        for (int j = 0; j < 16; j++) {
            const float2 p0 = __half22float2(*(const __half2*)&v[j].x);
            const float2 p1 = __half22float2(*(const __half2*)&v[j].y);
            acc.x += p0.x; acc.y += p0.y; acc.z += p1.x; acc.w += p1.y;
        }
    }

    const float4 bv = __ldg((const float4*)b + lane);
    acc.x = fmaxf(acc.x + bv.x, 0.f);
    acc.y = fmaxf(acc.y + bv.y, 0.f);
    acc.z = fmaxf(acc.z + bv.z, 0.f);
    acc.w = fmaxf(acc.w + bv.w, 0.f);

    ((float4*)(out + (size_t)n * MM))[lane] = acc;
}

// ---------------------------------------------------------------------------
// Launch: h, W, b, src, dst  ->  out [N, 128] fp32   (4 kernels total)
// ---------------------------------------------------------------------------
extern "C" void kernel_launch(void* const* d_in, const int* in_sizes, int n_in,
                              void* d_out, int out_size) {
    const float* h = (const float*)d_in[0];
    const float* W = (const float*)d_in[1];
    const float* b = (const float*)d_in[2];
    const int* src = (const int*)d_in[3];
    const int* dst = (const int*)d_in[4];
    float* out = (float*)d_out;

    const int E = in_sizes[3];

    static bool attr_set = false;
    if (!attr_set) {
        cudaFuncSetAttribute(gemm_scan_kernel,
                             cudaFuncAttributeMaxDynamicSharedMemorySize,
                             GEMM_SMEM);
        attr_set = true;
    }

    // K0: wfrag table + dst histogram (independent, one grid)
    {
        const int hist_blocks = (E + 255) / 256;
        prep_kernel<<<WFRAG_BLOCKS + hist_blocks, 256>>>(W, dst, E);
    }
    // K1: GEMM (blocks 1..) + full CSR scan (block 0, prefetch-pipelined)
    gemm_scan_kernel<<<1 + (NN + 63) / 64, 128, GEMM_SMEM>>>(h);

    // K2: CSR fill
    fill_kernel<<<(E + 255) / 256, 256>>>(src, dst, E);

    // K3: segmented reduce + bias + relu (one warp per node, 4 warps/block)
    {
        const long long threads = (long long)NN * 32;
        reduce_kernel<<<(int)((threads + 127) / 128), 128>>>(b, out);
    }
}

// round 12
// speedup vs baseline: 1.0393x; 1.0393x over previous
#include <cuda_runtime.h>
#include <cuda_fp16.h>
#include <cstdint>

typedef unsigned long long ull;

// Problem shape (fixed by the dataset)
#define NN 50000     // nodes
#define KK 256       // in feats
#define MM 128       // out feats
#define EE 800000    // edges

// Static scratch (no allocs allowed). Zero-initialized at load; reduce_kernel
// restores g_cnt to zero each launch, so the hist invariant holds every call.
__device__ __half g_hw[(size_t)NN * MM];  // h @ W in fp16 (12.8 MB, L2-resident)
__device__ int   g_cnt[NN];               // degree histogram (zero at entry)
__device__ int   g_off[NN];               // CSR exclusive offsets
__device__ int   g_pos[NN];               // fill cursors
__device__ int   g_srcs[EE];              // src ids grouped by dst
// Lane-ordered tf32 B-fragment table (built by prep_kernel blocks 0..63)
__device__ float4 g_wfrag4[32 * 512 / 2];        // 128 KB

__device__ __forceinline__ unsigned f2tf32(float x) {
    unsigned r;
    asm("cvt.rna.tf32.f32 %0, %1;" : "=r"(r) : "f"(x));
    return r;
}

// ---------------------------------------------------------------------------
// K0: prep — blocks 0..63 build W-fragment table; blocks 64.. histogram dst.
// ---------------------------------------------------------------------------
#define WFRAG_BLOCKS 64
__global__ __launch_bounds__(256)
void prep_kernel(const float* __restrict__ W, const int* __restrict__ dst, int E) {
    if (blockIdx.x < WFRAG_BLOCKS) {
        const int idx = blockIdx.x * 256 + threadIdx.x;   // 0 .. 16383
        const int kg = idx >> 9;          // k-step group 0..31
        const int r  = idx & 511;
        const int nt = r >> 5;            // 0..15
        const int le = r & 31;
        const int lq  = le & 3;
        const int ll4 = le >> 2;
        const int col = nt * 8 + ll4;
        const int k0  = kg * 8 + lq;
        float2* out = (float2*)g_wfrag4;
        out[idx] = make_float2(
            __uint_as_float(f2tf32(W[k0 * MM + col])),
            __uint_as_float(f2tf32(W[(k0 + 4) * MM + col])));
    } else {
        const int e = (blockIdx.x - WFRAG_BLOCKS) * 256 + threadIdx.x;
        if (e < E) atomicAdd(&g_cnt[dst[e]], 1);
    }
}

// ---------------------------------------------------------------------------
// K1: block 0 = full exclusive scan of g_cnt -> g_off,g_pos (prefetch-pipelined,
//     hidden under GEMM); blocks 1..782 = hw = h @ W via mma.sync m16n8k8 tf32.
// ---------------------------------------------------------------------------
#define HS_PAD 68
#define HS_FLOATS (64 * HS_PAD)                     // 4352 floats = 17408 B
#define GEMM_SMEM (HS_FLOATS * 4 + 8 * 512 * 8)     // 17408 + 32768 = 50176 B
#define SCAN_TILES ((NN + 511) / 512)               // 98
#define SCAN_PF 8

__device__ __forceinline__ int4 scan_load_tile(int t, int tid) {
    const int base = t * 512 + tid * 4;
    if (base + 3 < NN) return *(const int4*)&g_cnt[base];
    int4 v;
    v.x = (base     < NN) ? g_cnt[base]     : 0;
    v.y = (base + 1 < NN) ? g_cnt[base + 1] : 0;
    v.z = (base + 2 < NN) ? g_cnt[base + 2] : 0;
    v.w = (base + 3 < NN) ? g_cnt[base + 3] : 0;
    return v;
}

__device__ void scan_block_50k() {
    __shared__ int warp_tot[4];
    const int tid  = threadIdx.x;
    const int lane = tid & 31;
    const int warp = tid >> 5;
    int running = 0;

    int4 buf[SCAN_PF];
    #pragma unroll
    for (int t = 0; t < SCAN_PF; t++) buf[t] = scan_load_tile(t, tid);

    for (int tb = 0; tb < SCAN_TILES; tb += SCAN_PF) {
        #pragma unroll
        for (int j = 0; j < SCAN_PF; j++) {
            const int tile = tb + j;
            if (tile >= SCAN_TILES) break;
            const int4 v = buf[j];
            if (tile + SCAN_PF < SCAN_TILES)
                buf[j] = scan_load_tile(tile + SCAN_PF, tid);

            const int s0 = v.x, s1 = s0 + v.y, s2 = s1 + v.z, s3 = s2 + v.w;
            int x = s3;
            #pragma unroll
            for (int off = 1; off < 32; off <<= 1) {
                int y = __shfl_up_sync(0xffffffffu, x, off);
                if (lane >= off) x += y;
            }
            if (lane == 31) warp_tot[warp] = x;
            __syncthreads();
            int wb = 0;
            #pragma unroll
            for (int w = 0; w < 4; w++) if (w < warp) wb += warp_tot[w];
            const int tile_total = warp_tot[0] + warp_tot[1] + warp_tot[2] + warp_tot[3];
            const int bx = running + wb + (x - s3);

            const int base = tile * 512 + tid * 4;
            if (base     < NN) { g_off[base]     = bx;      g_pos[base]     = bx;      }
            if (base + 1 < NN) { g_off[base + 1] = bx + s0; g_pos[base + 1] = bx + s0; }
            if (base + 2 < NN) { g_off[base + 2] = bx + s1; g_pos[base + 2] = bx + s1; }
            if (base + 3 < NN) { g_off[base + 3] = bx + s2; g_pos[base + 3] = bx + s2; }

            running += tile_total;
            __syncthreads();
        }
    }
}

__global__ __launch_bounds__(128, 4)
void gemm_scan_kernel(const float* __restrict__ h) {
    if (blockIdx.x == 0) { scan_block_50k(); return; }

    extern __shared__ float smem[];
    float*  hs  = smem;                          // [64][HS_PAD]
    float2* Wk  = (float2*)(smem + HS_FLOATS);   // [8][512]
    float4* Wk4 = (float4*)Wk;

    const int tid  = threadIdx.x;
    const int warp = tid >> 5;
    const int lane = tid & 31;
    const int q    = lane & 3;    // k-offset within frag
    const int l4   = lane >> 2;   // row/col group

    const int blk_row0 = (blockIdx.x - 1) * 64;

    float d[16][4];
    #pragma unroll
    for (int nt = 0; nt < 16; nt++)
        #pragma unroll
        for (int j = 0; j < 4; j++) d[nt][j] = 0.f;

    for (int kc = 0; kc < 4; kc++) {            // 4 chunks of K=64
        if (kc) __syncthreads();                // drain readers before restage

        // stage B fragments: coalesced float4 copy (2048 float4, 16/thread)
        {
            const float4* src = g_wfrag4 + kc * (8 * 512 / 2);
            #pragma unroll
            for (int i = 0; i < 16; i++)
                Wk4[tid + i * 128] = __ldg(src + tid + i * 128);
        }
        // stage h chunk: 64 rows x 64 cols, tf32-converted (1024 float4, 8/thread)
        #pragma unroll
        for (int i = 0; i < 8; i++) {
            const int e   = tid + i * 128;      // 0..1023
            const int row = e >> 4;
            const int f4  = e & 15;
            int rg = blk_row0 + row;
            if (rg >= NN) rg = NN - 1;
            float4 v = __ldg((const float4*)(h + (size_t)rg * KK + kc * 64) + f4);
            v.x = __uint_as_float(f2tf32(v.x));
            v.y = __uint_as_float(f2tf32(v.y));
            v.z = __uint_as_float(f2tf32(v.z));
            v.w = __uint_as_float(f2tf32(v.w));
            ((float4*)(hs + row * HS_PAD))[f4] = v;
        }
        __syncthreads();

        #pragma unroll
        for (int ks = 0; ks < 8; ks++) {        // 8 k-steps of 8
            const int k8 = ks * 8;
            const int ar = warp * 16 + l4;
            const unsigned a0 = __float_as_uint(hs[(ar    ) * HS_PAD + k8 + q    ]);
            const unsigned a1 = __float_as_uint(hs[(ar + 8) * HS_PAD + k8 + q    ]);
            const unsigned a2 = __float_as_uint(hs[(ar    ) * HS_PAD + k8 + q + 4]);
            const unsigned a3 = __float_as_uint(hs[(ar + 8) * HS_PAD + k8 + q + 4]);
            const float2* wrow = Wk + ks * 512;

            #pragma unroll
            for (int nt = 0; nt < 16; nt++) {
                const float2 bb = wrow[nt * 32 + lane];   // coalesced LDS.64
                asm("mma.sync.aligned.m16n8k8.row.col.f32.tf32.tf32.f32 "
                    "{%0,%1,%2,%3}, {%4,%5,%6,%7}, {%8,%9}, {%0,%1,%2,%3};"
                    : "+f"(d[nt][0]), "+f"(d[nt][1]),
                      "+f"(d[nt][2]), "+f"(d[nt][3])
                    : "r"(a0), "r"(a1), "r"(a2), "r"(a3),
                      "r"(__float_as_uint(bb.x)), "r"(__float_as_uint(bb.y)));
            }
        }
    }

    // epilogue: fp16 store. d0,d1 at (l4, 2q..2q+1), d2,d3 at (l4+8, ..)
    const int r0 = blk_row0 + warp * 16 + l4;
    #pragma unroll
    for (int nt = 0; nt < 16; nt++) {
        const int col = nt * 8 + q * 2;
        if (r0 < NN)
            *(__half2*)(g_hw + (size_t)r0 * MM + col) =
                __floats2half2_rn(d[nt][0], d[nt][1]);
        if (r0 + 8 < NN)
            *(__half2*)(g_hw + (size_t)(r0 + 8) * MM + col) =
                __floats2half2_rn(d[nt][2], d[nt][3]);
    }
}

// ---------------------------------------------------------------------------
// K2: fill — bucket src ids into CSR order
// ---------------------------------------------------------------------------
__global__ void fill_kernel(const int* __restrict__ src, const int* __restrict__ dst, int E) {
    int e = blockIdx.x * blockDim.x + threadIdx.x;
    if (e < E) {
        int p = atomicAdd(&g_pos[dst[e]], 1);
        g_srcs[p] = src[e];
    }
}

// ---------------------------------------------------------------------------
// K3: segmented reduce v4 — cp.async gather into SMEM (register-free MLP).
//   One warp per node. Per batch of <=16 edges:
//     * one coalesced id-load + shfl distribution
//     * <=16 cp.async (8 B/lane, 256 B/row, coalesced) — fire-and-forget,
//       all 16 rows in flight regardless of register budget
//     * commit/wait, then conflict-free LDS.64 + fp32 accumulate
//   8 warps/block, 32 KB static smem -> 6 blocks/SM (48 warps) @ launch_bounds.
// ---------------------------------------------------------------------------
#define RED_WARPS 8
__global__ __launch_bounds__(256, 6)
void reduce_kernel(const float* __restrict__ b, float* __restrict__ out) {
    __shared__ __align__(16) uint2 sbuf[RED_WARPS][16][32];   // 32 KB

    const int warp = threadIdx.x >> 5;
    const int lane = threadIdx.x & 31;
    const int n = blockIdx.x * RED_WARPS + warp;
    if (n >= NN) return;

    const int beg = g_off[n];
    const int deg = g_cnt[n];
    if (lane == 0) g_cnt[n] = 0;   // restore invariant for next launch

    float4 acc = make_float4(0.f, 0.f, 0.f, 0.f);
    const uint2* __restrict__ hwp = (const uint2*)g_hw;   // 32 uint2 per row

    for (int base = 0; base < deg; base += 16) {
        const int m = min(deg - base, 16);   // warp-uniform
        int myid = 0;
        if (lane < m) myid = __ldg(&g_srcs[beg + base + lane]);

        #pragma unroll
        for (int j = 0; j < 16; j++) {
            if (j < m) {                      // uniform branch
                const int s = __shfl_sync(0xffffffffu, myid, j);
                const uint2* gsrc = hwp + (size_t)s * 32 + lane;
                const unsigned saddr =
                    (unsigned)__cvta_generic_to_shared(&sbuf[warp][j][lane]);
                asm volatile("cp.async.ca.shared.global [%0], [%1], 8;"
                             :: "r"(saddr), "l"(gsrc));
            }
        }
        asm volatile("cp.async.commit_group;");
        asm volatile("cp.async.wait_group 0;");
        __syncwarp();

        #pragma unroll
        for (int j = 0; j < 16; j++) {
            if (j < m) {                      // uniform branch
                const uint2 v = sbuf[warp][j][lane];
                const float2 p0 = __half22float2(*(const __half2*)&v.x);
                const float2 p1 = __half22float2(*(const __half2*)&v.y);
                acc.x += p0.x; acc.y += p0.y; acc.z += p1.x; acc.w += p1.y;
            }
        }
        __syncwarp();
    }

    const float4 bv = __ldg((const float4*)b + lane);
    acc.x = fmaxf(acc.x + bv.x, 0.f);
    acc.y = fmaxf(acc.y + bv.y, 0.f);
    acc.z = fmaxf(acc.z + bv.z, 0.f);
    acc.w = fmaxf(acc.w + bv.w, 0.f);

    ((float4*)(out + (size_t)n * MM))[lane] = acc;
}

// ---------------------------------------------------------------------------
// Launch: h, W, b, src, dst  ->  out [N, 128] fp32   (4 kernels total)
// ---------------------------------------------------------------------------
extern "C" void kernel_launch(void* const* d_in, const int* in_sizes, int n_in,
                              void* d_out, int out_size) {
    const float* h = (const float*)d_in[0];
    const float* W = (const float*)d_in[1];
    const float* b = (const float*)d_in[2];
    const int* src = (const int*)d_in[3];
    const int* dst = (const int*)d_in[4];
    float* out = (float*)d_out;

    const int E = in_sizes[3];

    static bool attr_set = false;
    if (!attr_set) {
        cudaFuncSetAttribute(gemm_scan_kernel,
                             cudaFuncAttributeMaxDynamicSharedMemorySize,
                             GEMM_SMEM);
        attr_set = true;
    }

    // K0: wfrag table + dst histogram (independent, one grid)
    {
        const int hist_blocks = (E + 255) / 256;
        prep_kernel<<<WFRAG_BLOCKS + hist_blocks, 256>>>(W, dst, E);
    }
    // K1: GEMM (blocks 1..) + full CSR scan (block 0, prefetch-pipelined)
    gemm_scan_kernel<<<1 + (NN + 63) / 64, 128, GEMM_SMEM>>>(h);

    // K2: CSR fill
    fill_kernel<<<(E + 255) / 256, 256>>>(src, dst, E);

    // K3: segmented reduce + bias + relu (one warp per node, cp.async gather)
    {
        const int blocks = (NN + RED_WARPS - 1) / RED_WARPS;
        reduce_kernel<<<blocks, 256>>>(b, out);
    }
}

// round 15
// speedup vs baseline: 1.3633x; 1.3117x over previous
#include <cuda_runtime.h>
#include <cuda_fp16.h>
#include <cstdint>

typedef unsigned long long ull;

// Problem shape (fixed by the dataset)
#define NN 50000     // nodes
#define KK 256       // in feats
#define MM 128       // out feats
#define EE 800000    // edges

// Static scratch (no allocs allowed). Zero-initialized at load; reduce_kernel
// restores g_cnt to zero each launch, so the hist invariant holds every call.
__device__ __half g_hw[(size_t)NN * MM];  // h @ W in fp16 (12.8 MB, L2-resident)
__device__ int   g_cnt[NN];               // degree histogram (zero at entry)
__device__ int   g_off[NN];               // CSR exclusive offsets
__device__ int   g_pos[NN];               // fill cursors
__device__ int   g_srcs[EE];              // src ids grouped by dst
// Lane-ordered tf32 B-fragment table (built by prep_kernel blocks 0..63)
__device__ float4 g_wfrag4[32 * 512 / 2];        // 128 KB

__device__ __forceinline__ unsigned f2tf32(float x) {
    unsigned r;
    asm("cvt.rna.tf32.f32 %0, %1;" : "=r"(r) : "f"(x));
    return r;
}

// ---------------------------------------------------------------------------
// K0: prep — blocks 0..63 build W-fragment table; blocks 64.. histogram dst.
// ---------------------------------------------------------------------------
#define WFRAG_BLOCKS 64
__global__ __launch_bounds__(256)
void prep_kernel(const float* __restrict__ W, const int* __restrict__ dst, int E) {
    if (blockIdx.x < WFRAG_BLOCKS) {
        const int idx = blockIdx.x * 256 + threadIdx.x;   // 0 .. 16383
        const int kg = idx >> 9;          // k-step group 0..31
        const int r  = idx & 511;
        const int nt = r >> 5;            // 0..15
        const int le = r & 31;
        const int lq  = le & 3;
        const int ll4 = le >> 2;
        const int col = nt * 8 + ll4;
        const int k0  = kg * 8 + lq;
        float2* out = (float2*)g_wfrag4;
        out[idx] = make_float2(
            __uint_as_float(f2tf32(W[k0 * MM + col])),
            __uint_as_float(f2tf32(W[(k0 + 4) * MM + col])));
    } else {
        const int e = (blockIdx.x - WFRAG_BLOCKS) * 256 + threadIdx.x;
        if (e < E) atomicAdd(&g_cnt[dst[e]], 1);
    }
}

// ---------------------------------------------------------------------------
// K1: block 0 = full exclusive scan of g_cnt -> g_off,g_pos (prefetch-pipelined,
//     hidden under GEMM); blocks 1..782 = hw = h @ W via mma.sync m16n8k8 tf32.
// ---------------------------------------------------------------------------
#define HS_PAD 68
#define HS_FLOATS (64 * HS_PAD)                     // 4352 floats = 17408 B
#define GEMM_SMEM (HS_FLOATS * 4 + 8 * 512 * 8)     // 17408 + 32768 = 50176 B
#define SCAN_TILES ((NN + 511) / 512)               // 98
#define SCAN_PF 8

__device__ __forceinline__ int4 scan_load_tile(int t, int tid) {
    const int base = t * 512 + tid * 4;
    if (base + 3 < NN) return *(const int4*)&g_cnt[base];
    int4 v;
    v.x = (base     < NN) ? g_cnt[base]     : 0;
    v.y = (base + 1 < NN) ? g_cnt[base + 1] : 0;
    v.z = (base + 2 < NN) ? g_cnt[base + 2] : 0;
    v.w = (base + 3 < NN) ? g_cnt[base + 3] : 0;
    return v;
}

__device__ void scan_block_50k() {
    __shared__ int warp_tot[4];
    const int tid  = threadIdx.x;
    const int lane = tid & 31;
    const int warp = tid >> 5;
    int running = 0;

    int4 buf[SCAN_PF];
    #pragma unroll
    for (int t = 0; t < SCAN_PF; t++) buf[t] = scan_load_tile(t, tid);

    for (int tb = 0; tb < SCAN_TILES; tb += SCAN_PF) {
        #pragma unroll
        for (int j = 0; j < SCAN_PF; j++) {
            const int tile = tb + j;
            if (tile >= SCAN_TILES) break;
            const int4 v = buf[j];
            if (tile + SCAN_PF < SCAN_TILES)
                buf[j] = scan_load_tile(tile + SCAN_PF, tid);

            const int s0 = v.x, s1 = s0 + v.y, s2 = s1 + v.z, s3 = s2 + v.w;
            int x = s3;
            #pragma unroll
            for (int off = 1; off < 32; off <<= 1) {
                int y = __shfl_up_sync(0xffffffffu, x, off);
                if (lane >= off) x += y;
            }
            if (lane == 31) warp_tot[warp] = x;
            __syncthreads();
            int wb = 0;
            #pragma unroll
            for (int w = 0; w < 4; w++) if (w < warp) wb += warp_tot[w];
            const int tile_total = warp_tot[0] + warp_tot[1] + warp_tot[2] + warp_tot[3];
            const int bx = running + wb + (x - s3);

            const int base = tile * 512 + tid * 4;
            if (base     < NN) { g_off[base]     = bx;      g_pos[base]     = bx;      }
            if (base + 1 < NN) { g_off[base + 1] = bx + s0; g_pos[base + 1] = bx + s0; }
            if (base + 2 < NN) { g_off[base + 2] = bx + s1; g_pos[base + 2] = bx + s1; }
            if (base + 3 < NN) { g_off[base + 3] = bx + s2; g_pos[base + 3] = bx + s2; }

            running += tile_total;
            __syncthreads();
        }
    }
}

__global__ __launch_bounds__(128, 4)
void gemm_scan_kernel(const float* __restrict__ h) {
    if (blockIdx.x == 0) { scan_block_50k(); return; }

    extern __shared__ float smem[];
    float*  hs  = smem;                          // [64][HS_PAD]
    float2* Wk  = (float2*)(smem + HS_FLOATS);   // [8][512]
    float4* Wk4 = (float4*)Wk;

    const int tid  = threadIdx.x;
    const int warp = tid >> 5;
    const int lane = tid & 31;
    const int q    = lane & 3;    // k-offset within frag
    const int l4   = lane >> 2;   // row/col group

    const int blk_row0 = (blockIdx.x - 1) * 64;

    float d[16][4];
    #pragma unroll
    for (int nt = 0; nt < 16; nt++)
        #pragma unroll
        for (int j = 0; j < 4; j++) d[nt][j] = 0.f;

    for (int kc = 0; kc < 4; kc++) {            // 4 chunks of K=64
        if (kc) __syncthreads();                // drain readers before restage

        // stage B fragments: coalesced float4 copy (2048 float4, 16/thread)
        {
            const float4* src = g_wfrag4 + kc * (8 * 512 / 2);
            #pragma unroll
            for (int i = 0; i < 16; i++)
                Wk4[tid + i * 128] = __ldg(src + tid + i * 128);
        }
        // stage h chunk: 64 rows x 64 cols, tf32-converted (1024 float4, 8/thread)
        #pragma unroll
        for (int i = 0; i < 8; i++) {
            const int e   = tid + i * 128;      // 0..1023
            const int row = e >> 4;
            const int f4  = e & 15;
            int rg = blk_row0 + row;
            if (rg >= NN) rg = NN - 1;
            float4 v = __ldg((const float4*)(h + (size_t)rg * KK + kc * 64) + f4);
            v.x = __uint_as_float(f2tf32(v.x));
            v.y = __uint_as_float(f2tf32(v.y));
            v.z = __uint_as_float(f2tf32(v.z));
            v.w = __uint_as_float(f2tf32(v.w));
            ((float4*)(hs + row * HS_PAD))[f4] = v;
        }
        __syncthreads();

        #pragma unroll
        for (int ks = 0; ks < 8; ks++) {        // 8 k-steps of 8
            const int k8 = ks * 8;
            const int ar = warp * 16 + l4;
            const unsigned a0 = __float_as_uint(hs[(ar    ) * HS_PAD + k8 + q    ]);
            const unsigned a1 = __float_as_uint(hs[(ar + 8) * HS_PAD + k8 + q    ]);
            const unsigned a2 = __float_as_uint(hs[(ar    ) * HS_PAD + k8 + q + 4]);
            const unsigned a3 = __float_as_uint(hs[(ar + 8) * HS_PAD + k8 + q + 4]);
            const float2* wrow = Wk + ks * 512;

            #pragma unroll
            for (int nt = 0; nt < 16; nt++) {
                const float2 bb = wrow[nt * 32 + lane];   // coalesced LDS.64
                asm("mma.sync.aligned.m16n8k8.row.col.f32.tf32.tf32.f32 "
                    "{%0,%1,%2,%3}, {%4,%5,%6,%7}, {%8,%9}, {%0,%1,%2,%3};"
                    : "+f"(d[nt][0]), "+f"(d[nt][1]),
                      "+f"(d[nt][2]), "+f"(d[nt][3])
                    : "r"(a0), "r"(a1), "r"(a2), "r"(a3),
                      "r"(__float_as_uint(bb.x)), "r"(__float_as_uint(bb.y)));
            }
        }
    }

    // epilogue: fp16 store. d0,d1 at (l4, 2q..2q+1), d2,d3 at (l4+8, ..)
    const int r0 = blk_row0 + warp * 16 + l4;
    #pragma unroll
    for (int nt = 0; nt < 16; nt++) {
        const int col = nt * 8 + q * 2;
        if (r0 < NN)
            *(__half2*)(g_hw + (size_t)r0 * MM + col) =
                __floats2half2_rn(d[nt][0], d[nt][1]);
        if (r0 + 8 < NN)
            *(__half2*)(g_hw + (size_t)(r0 + 8) * MM + col) =
                __floats2half2_rn(d[nt][2], d[nt][3]);
    }
}

// ---------------------------------------------------------------------------
// K2: fill — bucket src ids into CSR order
// ---------------------------------------------------------------------------
__global__ void fill_kernel(const int* __restrict__ src, const int* __restrict__ dst, int E) {
    int e = blockIdx.x * blockDim.x + threadIdx.x;
    if (e < E) {
        int p = atomicAdd(&g_pos[dst[e]], 1);
        g_srcs[p] = src[e];
    }
}

// ---------------------------------------------------------------------------
// K3: segmented reduce v5b — 8 nodes per warp, depth-2 cp.async pipeline.
//   Identical design to v5; the 64 KB buffer is now DYNAMIC shared memory
//   (static smem is capped at 48 KB — the v5 static 64 KB failed ptxas).
//   sbuf index: ((warp*2 + buf)*RB + j)*32 + lane
// ---------------------------------------------------------------------------
#define NPW 8
#define RB 16
#define RED_WARPS 8
#define RED_SMEM (RED_WARPS * 2 * RB * 32 * (int)sizeof(uint2))   // 65536 B

__device__ __forceinline__ bool next_item(int deg_l, int& k, int& base, int& m) {
    while (k < NPW) {
        const int d = __shfl_sync(0xffffffffu, deg_l, k);
        if (base < d) { m = min(d - base, RB); return true; }
        k++; base = 0;
    }
    return false;
}

__global__ __launch_bounds__(256)
void reduce_kernel(const float* __restrict__ b, float* __restrict__ out) {
    extern __shared__ __align__(16) uint2 sbuf[];   // [RED_WARPS][2][RB][32]

    const int warp = threadIdx.x >> 5;
    const int lane = threadIdx.x & 31;
    const int n0 = (blockIdx.x * RED_WARPS + warp) * NPW;
    if (n0 >= NN) return;

    uint2* wbuf = sbuf + warp * 2 * RB * 32;   // this warp's 2 buffers

    // per-node metadata, lane-parallel (lanes 0..NPW-1)
    int deg_l = 0, off_l = 0;
    if (lane < NPW && n0 + lane < NN) {
        deg_l = __ldg(&g_cnt[n0 + lane]);
        off_l = __ldg(&g_off[n0 + lane]);
        g_cnt[n0 + lane] = 0;    // restore invariant for next launch
    }
    const float4 bv = __ldg((const float4*)b + lane);
    const uint2* __restrict__ hwp = (const uint2*)g_hw;   // 32 uint2 per row

    // current issue item A
    int kA = 0, bA = 0, mA = 0;
    bool hasA = next_item(deg_l, kA, bA, mA);
    int idA = 0;
    if (hasA) {
        const int off = __shfl_sync(0xffffffffu, off_l, kA);
        if (lane < mA) idA = __ldg(&g_srcs[off + bA + lane]);
    }

    int buf = 0;
    int kP = -1, mP = 0, bufP = 0;     // pending-accumulate item
    float4 acc = make_float4(0.f, 0.f, 0.f, 0.f);
    int cur = -1;                       // node currently held in acc

    while (hasA) {
        // issue gathers for item A into wbuf[buf] (fire-and-forget)
        #pragma unroll
        for (int j = 0; j < RB; j++) {
            if (j < mA) {
                const int s = __shfl_sync(0xffffffffu, idA, j);
                const unsigned sa = (unsigned)__cvta_generic_to_shared(
                    &wbuf[(buf * RB + j) * 32 + lane]);
                asm volatile("cp.async.ca.shared.global [%0], [%1], 8;"
                             :: "r"(sa), "l"(hwp + (size_t)s * 32 + lane));
            }
        }
        asm volatile("cp.async.commit_group;");

        const int kI = kA, mI = mA, bufI = buf;

        // advance + prefetch next item's ids (overlaps in-flight group)
        bA += mA;
        hasA = next_item(deg_l, kA, bA, mA);
        int idN = 0;
        if (hasA) {
            const int off = __shfl_sync(0xffffffffu, off_l, kA);
            if (lane < mA) idN = __ldg(&g_srcs[off + bA + lane]);
        }

        // accumulate previous item while current group is in flight
        if (kP >= 0) {
            asm volatile("cp.async.wait_group 1;");
            if (kP != cur) {
                if (cur >= 0) {
                    float4 r;
                    r.x = fmaxf(acc.x + bv.x, 0.f);
                    r.y = fmaxf(acc.y + bv.y, 0.f);
                    r.z = fmaxf(acc.z + bv.z, 0.f);
                    r.w = fmaxf(acc.w + bv.w, 0.f);
                    ((float4*)(out + (size_t)(n0 + cur) * MM))[lane] = r;
                }
                acc = make_float4(0.f, 0.f, 0.f, 0.f);
                cur = kP;
            }
            #pragma unroll
            for (int j = 0; j < RB; j++) {
                if (j < mP) {
                    const uint2 v = wbuf[(bufP * RB + j) * 32 + lane];
                    const float2 p0 = __half22float2(*(const __half2*)&v.x);
                    const float2 p1 = __half22float2(*(const __half2*)&v.y);
                    acc.x += p0.x; acc.y += p0.y; acc.z += p1.x; acc.w += p1.y;
                }
            }
        }
        kP = kI; mP = mI; bufP = bufI;
        idA = idN;
        buf ^= 1;
    }

    // epilogue: last pending item
    if (kP >= 0) {
        asm volatile("cp.async.wait_group 0;");
        if (kP != cur) {
            if (cur >= 0) {
                float4 r;
                r.x = fmaxf(acc.x + bv.x, 0.f);
                r.y = fmaxf(acc.y + bv.y, 0.f);
                r.z = fmaxf(acc.z + bv.z, 0.f);
                r.w = fmaxf(acc.w + bv.w, 0.f);
                ((float4*)(out + (size_t)(n0 + cur) * MM))[lane] = r;
            }
            acc = make_float4(0.f, 0.f, 0.f, 0.f);
            cur = kP;
        }
        #pragma unroll
        for (int j = 0; j < RB; j++) {
            if (j < mP) {
                const uint2 v = wbuf[(bufP * RB + j) * 32 + lane];
                const float2 p0 = __half22float2(*(const __half2*)&v.x);
                const float2 p1 = __half22float2(*(const __half2*)&v.y);
                acc.x += p0.x; acc.y += p0.y; acc.z += p1.x; acc.w += p1.y;
            }
        }
    }
    if (cur >= 0) {
        float4 r;
        r.x = fmaxf(acc.x + bv.x, 0.f);
        r.y = fmaxf(acc.y + bv.y, 0.f);
        r.z = fmaxf(acc.z + bv.z, 0.f);
        r.w = fmaxf(acc.w + bv.w, 0.f);
        ((float4*)(out + (size_t)(n0 + cur) * MM))[lane] = r;
    }

    // deg-0 nodes: out = relu(b)
    #pragma unroll
    for (int k = 0; k < NPW; k++) {
        const int d = __shfl_sync(0xffffffffu, deg_l, k);
        if (d == 0 && n0 + k < NN) {
            float4 r;
            r.x = fmaxf(bv.x, 0.f);
            r.y = fmaxf(bv.y, 0.f);
            r.z = fmaxf(bv.z, 0.f);
            r.w = fmaxf(bv.w, 0.f);
            ((float4*)(out + (size_t)(n0 + k) * MM))[lane] = r;
        }
    }
}

// ---------------------------------------------------------------------------
// Launch: h, W, b, src, dst  ->  out [N, 128] fp32   (4 kernels total)
// ---------------------------------------------------------------------------
extern "C" void kernel_launch(void* const* d_in, const int* in_sizes, int n_in,
                              void* d_out, int out_size) {
    const float* h = (const float*)d_in[0];
    const float* W = (const float*)d_in[1];
    const float* b = (const float*)d_in[2];
    const int* src = (const int*)d_in[3];
    const int* dst = (const int*)d_in[4];
    float* out = (float*)d_out;

    const int E = in_sizes[3];

    static bool attr_set = false;
    if (!attr_set) {
        cudaFuncSetAttribute(gemm_scan_kernel,
                             cudaFuncAttributeMaxDynamicSharedMemorySize,
                             GEMM_SMEM);
        cudaFuncSetAttribute(reduce_kernel,
                             cudaFuncAttributeMaxDynamicSharedMemorySize,
                             RED_SMEM);
        attr_set = true;
    }

    // K0: wfrag table + dst histogram (independent, one grid)
    {
        const int hist_blocks = (E + 255) / 256;
        prep_kernel<<<WFRAG_BLOCKS + hist_blocks, 256>>>(W, dst, E);
    }
    // K1: GEMM (blocks 1..) + full CSR scan (block 0, prefetch-pipelined)
    gemm_scan_kernel<<<1 + (NN + 63) / 64, 128, GEMM_SMEM>>>(h);

    // K2: CSR fill
    fill_kernel<<<(E + 255) / 256, 256>>>(src, dst, E);

    // K3: segmented reduce + bias + relu (8 nodes/warp, pipelined cp.async)
    {
        const int warps = (NN + NPW - 1) / NPW;                  // 6250
        const int blocks = (warps + RED_WARPS - 1) / RED_WARPS;  // 782
        reduce_kernel<<<blocks, 256, RED_SMEM>>>(b, out);
    }
}